// round 15
// baseline (speedup 1.0000x reference)
#include <cuda_runtime.h>
#include <cuda_fp16.h>
#include <cstdint>

// Y = X @ (W_nf4 * c1 * c_kbit_2) + (X@L1)@L2  ==  X @ W'  with
//   W' = W_nf4*c1*c_kbit_2 + L1@L2   (rank-16 update folded into the weight)
// R14->R15: fuse pack_w (4096 blocks, first) + pack_x (32768 tiny blocks,
// backfill) into ONE kernel. Both are DRAM-bound and fine-grained now, so
// block-range fusion approaches the joint memory floor (~44us) instead of
// serializing (64.8us). GEMM byte-identical to R12/R14 (KPAD=4160, R6/R8
// pipeline, KT=64).
//   Xe fp16 [8192,4160] (cols 0..4095 = fp16(X))
//   We fp16 [4096,4160] (cols 0..4095 = fp16(W^T + (L1@L2)^T))

static constexpr int D_IN  = 4096;
static constexpr int D_OUT = 4096;
static constexpr int NROWS = 8192;
static constexpr int KPAD  = 4160;    // 8320B stride = 65 x 128B (proven)

static constexpr int BM = 128, BN = 128, BK = 64, S = 3;
static constexpr int KT = D_IN / BK;              // 64
static constexpr int ABYTES = BM * BK * 2;        // 16384
static constexpr int BBYTES = BN * BK * 2;        // 16384
static constexpr int STAGE  = ABYTES + BBYTES;    // 32768
static constexpr int SMEM_SZ = S * STAGE;         // 98304 (2 CTAs/SM)

static constexpr int PW_BLOCKS = (D_OUT / 64) * (D_IN / 64);    // 4096
static constexpr int PX_BLOCKS = (NROWS * D_IN / 4) / 256;      // 32768
static constexpr int PACK_BLOCKS = PW_BLOCKS + PX_BLOCKS;       // 36864

__device__ __align__(16) __half g_Xe[(size_t)NROWS * KPAD];   // 68 MB
__device__ __align__(16) __half g_We[(size_t)D_OUT * KPAD];   // 34 MB

// ------------------------------ PTX helpers -------------------------------
__device__ __forceinline__ void cp16(uint32_t dst, const void* src) {
    asm volatile("cp.async.cg.shared.global [%0], [%1], 16;"
                 :: "r"(dst), "l"(__cvta_generic_to_global(src)) : "memory");
}
#define CP_COMMIT() asm volatile("cp.async.commit_group;" ::: "memory")
#define CP_WAIT(n)  asm volatile("cp.async.wait_group %0;" :: "n"(n) : "memory")

#define LDSM4(r, a) \
    asm volatile("ldmatrix.sync.aligned.m8n8.x4.shared.b16 {%0,%1,%2,%3}, [%4];" \
        : "=r"((r)[0]), "=r"((r)[1]), "=r"((r)[2]), "=r"((r)[3]) : "r"(a))

#define MMA16816(d, a, b) \
    asm volatile("mma.sync.aligned.m16n8k16.row.col.f32.f16.f16.f32 " \
        "{%0,%1,%2,%3}, {%4,%5,%6,%7}, {%8,%9}, {%0,%1,%2,%3};" \
        : "+f"((d)[0]), "+f"((d)[1]), "+f"((d)[2]), "+f"((d)[3]) \
        : "r"((a)[0]), "r"((a)[1]), "r"((a)[2]), "r"((a)[3]), \
          "r"((b)[0]), "r"((b)[1]))

__device__ __forceinline__ uint32_t swz(uint32_t o) { return o ^ ((o >> 3) & 0x70); }

// ----------------- fused pack: blocks [0,4096)=W, rest=X -------------------
__global__ void __launch_bounds__(256)
pack_kernel(const float* __restrict__ X,  const float* __restrict__ Wq,
            const float* __restrict__ c1p, const float* __restrict__ ck,
            const float* __restrict__ L1, const float* __restrict__ L2) {
    __shared__ float tile[64 * 65];      // dequantized W tile, tile[k*65+n]
    __shared__ float sL1[64 * 17];       // L1[k0+k][j]  at sL1[k*17+j]
    __shared__ float sL2[16 * 68];       // L2[j][n0+n] at sL2[j*68+n]
    const int bid = blockIdx.x;
    const int tid = threadIdx.x;

    if (bid < PW_BLOCKS) {
        // ---------------- pack_w: dequant + LoRA + transpose ----------------
        const float c1 = *c1p;
        const int n0 = (bid & 63) * 64, k0 = (bid >> 6) * 64;

        {   // Phase 1: float4 dequant into smem + L1/L2 tiles
            const int tq = tid & 15, tr = tid >> 4;
#pragma unroll
            for (int i = 0; i < 4; i++) {
                int kk = tr + 16 * i;
                int nc = tq * 4;
                size_t g = (size_t)(k0 + kk) * D_OUT + n0 + nc;
                float4 w = *(const float4*)(Wq + g);
                float4 s = *(const float4*)(ck + g);
                float* tp = tile + kk * 65 + nc;
                tp[0] = w.x * c1 * s.x;
                tp[1] = w.y * c1 * s.y;
                tp[2] = w.z * c1 * s.z;
                tp[3] = w.w * c1 * s.w;
            }
            int kr = tid >> 2, j4 = (tid & 3) * 4;
            float4 v1 = *(const float4*)(L1 + (size_t)(k0 + kr) * 16 + j4);
            float* lp = sL1 + kr * 17 + j4;
            lp[0] = v1.x; lp[1] = v1.y; lp[2] = v1.z; lp[3] = v1.w;
            int jj = tid >> 4, c = (tid & 15) * 4;
            float4 v2 = *(const float4*)(L2 + (size_t)jj * D_OUT + n0 + c);
            *(float4*)(sL2 + jj * 68 + c) = v2;
        }
        __syncthreads();

        // Phase 2: 4k x 4n sub-block per thread (outer-product LoRA)
        const int k4 = (tid & 15) * 4;
        const int n4 = (tid >> 4) * 4;
        float acc[4][4];
#pragma unroll
        for (int i = 0; i < 4; i++)
#pragma unroll
            for (int q = 0; q < 4; q++)
                acc[i][q] = tile[(k4 + i) * 65 + n4 + q];

#pragma unroll
        for (int j = 0; j < 16; j++) {
            float l2q[4], l1i[4];
#pragma unroll
            for (int q = 0; q < 4; q++) l2q[q] = sL2[j * 68 + n4 + q];
#pragma unroll
            for (int i = 0; i < 4; i++) l1i[i] = sL1[(k4 + i) * 17 + j];
#pragma unroll
            for (int i = 0; i < 4; i++)
#pragma unroll
                for (int q = 0; q < 4; q++)
                    acc[i][q] += l1i[i] * l2q[q];
        }

#pragma unroll
        for (int q = 0; q < 4; q++) {
            __half2 h0 = __floats2half2_rn(acc[0][q], acc[1][q]);
            __half2 h1 = __floats2half2_rn(acc[2][q], acc[3][q]);
            uint2 u;
            u.x = *(uint32_t*)&h0;
            u.y = *(uint32_t*)&h1;
            *(uint2*)(g_We + (size_t)(n0 + n4 + q) * KPAD + k0 + k4) = u;
        }
    } else {
        // ---------------- pack_x: fp32 -> fp16 convert ----------------------
        size_t e = ((size_t)(bid - PW_BLOCKS) * 256 + tid) * 4;
        size_t row = e >> 12, col = e & 4095;
        float4 v = *(const float4*)(X + e);
        __half* dst = g_Xe + row * KPAD + col;
        *(__half2*)(dst)     = __floats2half2_rn(v.x, v.y);
        *(__half2*)(dst + 2) = __floats2half2_rn(v.z, v.w);
    }
}

// ------------------------------ GEMM kernel --------------------------------
// Exact R6/R8 loop: 4 warps (2x2), warp tile 64x64, cross-iteration frag
// prefetch with deferred commit_group; sync -> load_frag(1) -> mma(0).
__global__ void __launch_bounds__(128, 2)
gemm_kernel(float* __restrict__ Y) {
    extern __shared__ char smem[];
    const uint32_t sb = (uint32_t)__cvta_generic_to_shared(smem);
    const int tid = threadIdx.x, wid = tid >> 5, lane = tid & 31;
    const int m0 = blockIdx.y * BM, n0 = blockIdx.x * BN;
    const int wm = wid & 1, wn = wid >> 1;
    const int gid = lane >> 2, tig = lane & 3;

    auto loadA = [&](int kt, int slot) {
        const __half* src = g_Xe + (size_t)m0 * KPAD + (size_t)kt * BK;
        uint32_t base = sb + slot * STAGE;
#pragma unroll
        for (int i = 0; i < 8; i++) {
            int idx = tid + i * 128;
            int r = idx >> 3, c = idx & 7;
            cp16(base + swz((uint32_t)(r * 128 + c * 16)),
                 src + (size_t)r * KPAD + c * 8);
        }
    };
    auto loadB = [&](int kt, int slot) {
        const __half* src = g_We + (size_t)n0 * KPAD + (size_t)kt * BK;
        uint32_t base = sb + slot * STAGE + ABYTES;
#pragma unroll
        for (int i = 0; i < 8; i++) {
            int idx = tid + i * 128;
            int r = idx >> 3, c = idx & 7;
            cp16(base + swz((uint32_t)(r * 128 + c * 16)),
                 src + (size_t)r * KPAD + c * 8);
        }
    };

    float acc[4][8][4];
#pragma unroll
    for (int t = 0; t < 4; t++)
#pragma unroll
        for (int n = 0; n < 8; n++)
#pragma unroll
            for (int j = 0; j < 4; j++) acc[t][n][j] = 0.f;

#pragma unroll
    for (int s = 0; s < S - 1; s++) { loadA(s, s); loadB(s, s); CP_COMMIT(); }

    const uint32_t a_row = (uint32_t)(wm * 64 + (lane & 15));
    const uint32_t a_chk = (uint32_t)(lane >> 4);
    const uint32_t b_row = (uint32_t)(wn * 64 + ((lane >> 4) & 1) * 8 + (lane & 7));
    const uint32_t b_chk = (uint32_t)((lane >> 3) & 1);

    uint32_t af[2][4][4];
    uint32_t bf[2][8][2];

    auto load_frag = [&](int buf, uint32_t abase, int ks) {
        const uint32_t bbase = abase + ABYTES;
#pragma unroll
        for (int t = 0; t < 4; t++) {
            uint32_t off = (a_row + t * 16) * 128 + (a_chk + ks * 2) * 16;
            LDSM4(af[buf][t], abase + swz(off));
        }
#pragma unroll
        for (int g = 0; g < 4; g++) {
            uint32_t off = (b_row + g * 16) * 128 + (b_chk + ks * 2) * 16;
            uint32_t r[4];
            LDSM4(r, bbase + swz(off));
            bf[buf][2 * g][0] = r[0];     bf[buf][2 * g][1] = r[1];
            bf[buf][2 * g + 1][0] = r[2]; bf[buf][2 * g + 1][1] = r[3];
        }
    };
    auto mma_block = [&](int buf) {
#pragma unroll
        for (int t = 0; t < 4; t++)
#pragma unroll
            for (int n = 0; n < 8; n++)
                MMA16816(acc[t][n], af[buf][t], bf[buf][n]);
    };

    // Wait stage 0 (leave stage 1 in flight), prefetch its ks=0 fragments.
    CP_WAIT(1);
    __syncthreads();
    load_frag(0, sb + 0 * STAGE, 0);

    for (int kt = 0; kt < KT; kt++) {
        const uint32_t abase = sb + (kt % S) * STAGE;
        // Barrier: about to overwrite slot (kt+2)%S == (kt-1)%S. All reads of
        // stage kt-1 (and the prefetch read of stage kt) happened before here.
        __syncthreads();

        load_frag(1, abase, 1);          // ks=1 frags first (critical path)
        mma_block(0);                    // ks=0 (prefetched)

        if (kt + 2 < KT) {               // issue next stage UNCOMMITTED
            loadA(kt + 2, (kt + 2) % S);
            loadB(kt + 2, (kt + 2) % S);
        }

        load_frag(0, abase, 2);
        mma_block(1);                    // ks=1

        load_frag(1, abase, 3);
        mma_block(0);                    // ks=2

        if (kt + 1 < KT) {
            CP_WAIT(0);                  // drains stage kt+1 only (kt+2 uncommitted)
            load_frag(0, sb + ((kt + 1) % S) * STAGE, 0);   // prefetch next ks=0
        }
        mma_block(1);                    // ks=3
        CP_COMMIT();                     // name stage kt+2's group
    }

    // Epilogue: direct float2 stores
#pragma unroll
    for (int t = 0; t < 4; t++) {
        const int r0 = m0 + wm * 64 + t * 16 + gid;
        float* y0 = Y + (size_t)r0 * D_OUT + n0 + wn * 64 + tig * 2;
        float* y1 = y0 + (size_t)8 * D_OUT;
#pragma unroll
        for (int n = 0; n < 8; n++) {
            *(float2*)(y0 + n * 8) = make_float2(acc[t][n][0], acc[t][n][1]);
            *(float2*)(y1 + n * 8) = make_float2(acc[t][n][2], acc[t][n][3]);
        }
    }
}

// ------------------------------- launcher ----------------------------------
extern "C" void kernel_launch(void* const* d_in, const int* in_sizes, int n_in,
                              void* d_out, int out_size) {
    const float* X  = (const float*)d_in[0];
    const float* Wq = (const float*)d_in[1];
    const float* c1 = (const float*)d_in[2];
    const float* ck = (const float*)d_in[3];
    const float* L1 = (const float*)d_in[4];
    const float* L2 = (const float*)d_in[5];
    float* Y = (float*)d_out;

    cudaFuncSetAttribute(gemm_kernel, cudaFuncAttributeMaxDynamicSharedMemorySize, SMEM_SZ);

    pack_kernel<<<PACK_BLOCKS, 256>>>(X, Wq, c1, ck, L1, L2);
    gemm_kernel<<<dim3(D_OUT / BN, NROWS / BM), 128, SMEM_SZ>>>(Y);
}

// round 16
// speedup vs baseline: 1.0178x; 1.0178x over previous
#include <cuda_runtime.h>
#include <cuda_fp16.h>
#include <cstdint>

// Y = X @ (W_nf4 * c1 * c_kbit_2) + (X@L1)@L2  ==  X @ W'  with
//   W' = W_nf4*c1*c_kbit_2 + L1@L2   (rank-16 update folded into the weight)
// R15->R16: revert pack fusion (two independent fine-grained kernels beat the
// fused grid twice now; keep split permanently). Coarsen pack_x: one block
// per row, 16 elems/thread, uint4 (128-bit) stores. pack_w + GEMM
// byte-identical to R14 (KPAD=4160 proven stride, R6/R8 GEMM pipeline, KT=64).
//   Xe fp16 [8192,4160] (cols 0..4095 = fp16(X))
//   We fp16 [4096,4160] (cols 0..4095 = fp16(W^T + (L1@L2)^T))

static constexpr int D_IN  = 4096;
static constexpr int D_OUT = 4096;
static constexpr int NROWS = 8192;
static constexpr int KPAD  = 4160;    // 8320B stride = 65 x 128B (proven)

static constexpr int BM = 128, BN = 128, BK = 64, S = 3;
static constexpr int KT = D_IN / BK;              // 64
static constexpr int ABYTES = BM * BK * 2;        // 16384
static constexpr int BBYTES = BN * BK * 2;        // 16384
static constexpr int STAGE  = ABYTES + BBYTES;    // 32768
static constexpr int SMEM_SZ = S * STAGE;         // 98304 (2 CTAs/SM)

__device__ __align__(16) __half g_Xe[(size_t)NROWS * KPAD];   // 68 MB
__device__ __align__(16) __half g_We[(size_t)D_OUT * KPAD];   // 34 MB

// ------------------------------ PTX helpers -------------------------------
__device__ __forceinline__ void cp16(uint32_t dst, const void* src) {
    asm volatile("cp.async.cg.shared.global [%0], [%1], 16;"
                 :: "r"(dst), "l"(__cvta_generic_to_global(src)) : "memory");
}
#define CP_COMMIT() asm volatile("cp.async.commit_group;" ::: "memory")
#define CP_WAIT(n)  asm volatile("cp.async.wait_group %0;" :: "n"(n) : "memory")

#define LDSM4(r, a) \
    asm volatile("ldmatrix.sync.aligned.m8n8.x4.shared.b16 {%0,%1,%2,%3}, [%4];" \
        : "=r"((r)[0]), "=r"((r)[1]), "=r"((r)[2]), "=r"((r)[3]) : "r"(a))

#define MMA16816(d, a, b) \
    asm volatile("mma.sync.aligned.m16n8k16.row.col.f32.f16.f16.f32 " \
        "{%0,%1,%2,%3}, {%4,%5,%6,%7}, {%8,%9}, {%0,%1,%2,%3};" \
        : "+f"((d)[0]), "+f"((d)[1]), "+f"((d)[2]), "+f"((d)[3]) \
        : "r"((a)[0]), "r"((a)[1]), "r"((a)[2]), "r"((a)[3]), \
          "r"((b)[0]), "r"((b)[1]))

__device__ __forceinline__ uint32_t swz(uint32_t o) { return o ^ ((o >> 3) & 0x70); }

// ------------------- pack_X: fp32 -> fp16 convert (padded rows) ------------
// One block per row. 16 elems/thread: 2 x (two float4 loads -> one uint4
// store). Warp loads cover contiguous 4KB; stores contiguous 512B.
__global__ void __launch_bounds__(256)
pack_x_kernel(const float* __restrict__ X) {
    const size_t row = blockIdx.x;
    const float* src = X + row * (size_t)D_IN;
    __half* dst = g_Xe + row * (size_t)KPAD;
#pragma unroll
    for (int i = 0; i < 2; i++) {
        const int c = threadIdx.x * 8 + i * 2048;
        float4 a = *(const float4*)(src + c);
        float4 b = *(const float4*)(src + c + 4);
        __half2 t0 = __floats2half2_rn(a.x, a.y);
        __half2 t1 = __floats2half2_rn(a.z, a.w);
        __half2 t2 = __floats2half2_rn(b.x, b.y);
        __half2 t3 = __floats2half2_rn(b.z, b.w);
        uint4 u;
        u.x = *(uint32_t*)&t0;
        u.y = *(uint32_t*)&t1;
        u.z = *(uint32_t*)&t2;
        u.w = *(uint32_t*)&t3;
        *(uint4*)(dst + c) = u;
    }
}

// -------- pack_W: dequant + rank-16 LoRA add + transpose to We -------------
// 64x64 tile per block. Phase 1: float4 dequant into smem tile[k][n] (+L1/L2
// tiles). Phase 2: each thread owns a 4k x 4n sub-block: outer-product LoRA
// accumulation, then uint2 stores of 4 k-contiguous halfs (coalesced).
__global__ void __launch_bounds__(256)
pack_w_kernel(const float* __restrict__ Wq, const float* __restrict__ c1p,
              const float* __restrict__ ck, const float* __restrict__ L1,
              const float* __restrict__ L2) {
    __shared__ float tile[64 * 65];      // dequantized W tile, tile[k*65+n]
    __shared__ float sL1[64 * 17];       // L1[k0+k][j]  at sL1[k*17+j]
    __shared__ float sL2[16 * 68];       // L2[j][n0+n] at sL2[j*68+n]
    const float c1 = *c1p;
    const int tid = threadIdx.x;
    const int n0 = blockIdx.x * 64, k0 = blockIdx.y * 64;

    // Phase 1: dequant 64x64 via float4 (4 rows x 16 n-groups per iter)
    {
        const int tq = tid & 15, tr = tid >> 4;
#pragma unroll
        for (int i = 0; i < 4; i++) {
            int kk = tr + 16 * i;
            int nc = tq * 4;
            size_t g = (size_t)(k0 + kk) * D_OUT + n0 + nc;
            float4 w = *(const float4*)(Wq + g);
            float4 s = *(const float4*)(ck + g);
            float* tp = tile + kk * 65 + nc;
            tp[0] = w.x * c1 * s.x;
            tp[1] = w.y * c1 * s.y;
            tp[2] = w.z * c1 * s.z;
            tp[3] = w.w * c1 * s.w;
        }
        int kr = tid >> 2, j4 = (tid & 3) * 4;
        float4 v1 = *(const float4*)(L1 + (size_t)(k0 + kr) * 16 + j4);
        float* lp = sL1 + kr * 17 + j4;
        lp[0] = v1.x; lp[1] = v1.y; lp[2] = v1.z; lp[3] = v1.w;
        int jj = tid >> 4, c = (tid & 15) * 4;
        float4 v2 = *(const float4*)(L2 + (size_t)jj * D_OUT + n0 + c);
        *(float4*)(sL2 + jj * 68 + c) = v2;
    }
    __syncthreads();

    // Phase 2: 4k x 4n sub-block per thread
    const int k4 = (tid & 15) * 4;       // k base (lane-contiguous for stores)
    const int n4 = (tid >> 4) * 4;       // n base
    float acc[4][4];
#pragma unroll
    for (int i = 0; i < 4; i++)
#pragma unroll
        for (int q = 0; q < 4; q++)
            acc[i][q] = tile[(k4 + i) * 65 + n4 + q];

#pragma unroll
    for (int j = 0; j < 16; j++) {
        float l2q[4], l1i[4];
#pragma unroll
        for (int q = 0; q < 4; q++) l2q[q] = sL2[j * 68 + n4 + q];
#pragma unroll
        for (int i = 0; i < 4; i++) l1i[i] = sL1[(k4 + i) * 17 + j];
#pragma unroll
        for (int i = 0; i < 4; i++)
#pragma unroll
            for (int q = 0; q < 4; q++)
                acc[i][q] += l1i[i] * l2q[q];
    }

#pragma unroll
    for (int q = 0; q < 4; q++) {
        __half2 h0 = __floats2half2_rn(acc[0][q], acc[1][q]);
        __half2 h1 = __floats2half2_rn(acc[2][q], acc[3][q]);
        uint2 u;
        u.x = *(uint32_t*)&h0;
        u.y = *(uint32_t*)&h1;
        *(uint2*)(g_We + (size_t)(n0 + n4 + q) * KPAD + k0 + k4) = u;
    }
}

// ------------------------------ GEMM kernel --------------------------------
// Exact R6/R8 loop: 4 warps (2x2), warp tile 64x64, cross-iteration frag
// prefetch with deferred commit_group; sync -> load_frag(1) -> mma(0).
__global__ void __launch_bounds__(128, 2)
gemm_kernel(float* __restrict__ Y) {
    extern __shared__ char smem[];
    const uint32_t sb = (uint32_t)__cvta_generic_to_shared(smem);
    const int tid = threadIdx.x, wid = tid >> 5, lane = tid & 31;
    const int m0 = blockIdx.y * BM, n0 = blockIdx.x * BN;
    const int wm = wid & 1, wn = wid >> 1;
    const int gid = lane >> 2, tig = lane & 3;

    auto loadA = [&](int kt, int slot) {
        const __half* src = g_Xe + (size_t)m0 * KPAD + (size_t)kt * BK;
        uint32_t base = sb + slot * STAGE;
#pragma unroll
        for (int i = 0; i < 8; i++) {
            int idx = tid + i * 128;
            int r = idx >> 3, c = idx & 7;
            cp16(base + swz((uint32_t)(r * 128 + c * 16)),
                 src + (size_t)r * KPAD + c * 8);
        }
    };
    auto loadB = [&](int kt, int slot) {
        const __half* src = g_We + (size_t)n0 * KPAD + (size_t)kt * BK;
        uint32_t base = sb + slot * STAGE + ABYTES;
#pragma unroll
        for (int i = 0; i < 8; i++) {
            int idx = tid + i * 128;
            int r = idx >> 3, c = idx & 7;
            cp16(base + swz((uint32_t)(r * 128 + c * 16)),
                 src + (size_t)r * KPAD + c * 8);
        }
    };

    float acc[4][8][4];
#pragma unroll
    for (int t = 0; t < 4; t++)
#pragma unroll
        for (int n = 0; n < 8; n++)
#pragma unroll
            for (int j = 0; j < 4; j++) acc[t][n][j] = 0.f;

#pragma unroll
    for (int s = 0; s < S - 1; s++) { loadA(s, s); loadB(s, s); CP_COMMIT(); }

    const uint32_t a_row = (uint32_t)(wm * 64 + (lane & 15));
    const uint32_t a_chk = (uint32_t)(lane >> 4);
    const uint32_t b_row = (uint32_t)(wn * 64 + ((lane >> 4) & 1) * 8 + (lane & 7));
    const uint32_t b_chk = (uint32_t)((lane >> 3) & 1);

    uint32_t af[2][4][4];
    uint32_t bf[2][8][2];

    auto load_frag = [&](int buf, uint32_t abase, int ks) {
        const uint32_t bbase = abase + ABYTES;
#pragma unroll
        for (int t = 0; t < 4; t++) {
            uint32_t off = (a_row + t * 16) * 128 + (a_chk + ks * 2) * 16;
            LDSM4(af[buf][t], abase + swz(off));
        }
#pragma unroll
        for (int g = 0; g < 4; g++) {
            uint32_t off = (b_row + g * 16) * 128 + (b_chk + ks * 2) * 16;
            uint32_t r[4];
            LDSM4(r, bbase + swz(off));
            bf[buf][2 * g][0] = r[0];     bf[buf][2 * g][1] = r[1];
            bf[buf][2 * g + 1][0] = r[2]; bf[buf][2 * g + 1][1] = r[3];
        }
    };
    auto mma_block = [&](int buf) {
#pragma unroll
        for (int t = 0; t < 4; t++)
#pragma unroll
            for (int n = 0; n < 8; n++)
                MMA16816(acc[t][n], af[buf][t], bf[buf][n]);
    };

    // Wait stage 0 (leave stage 1 in flight), prefetch its ks=0 fragments.
    CP_WAIT(1);
    __syncthreads();
    load_frag(0, sb + 0 * STAGE, 0);

    for (int kt = 0; kt < KT; kt++) {
        const uint32_t abase = sb + (kt % S) * STAGE;
        // Barrier: about to overwrite slot (kt+2)%S == (kt-1)%S. All reads of
        // stage kt-1 (and the prefetch read of stage kt) happened before here.
        __syncthreads();

        load_frag(1, abase, 1);          // ks=1 frags first (critical path)
        mma_block(0);                    // ks=0 (prefetched)

        if (kt + 2 < KT) {               // issue next stage UNCOMMITTED
            loadA(kt + 2, (kt + 2) % S);
            loadB(kt + 2, (kt + 2) % S);
        }

        load_frag(0, abase, 2);
        mma_block(1);                    // ks=1

        load_frag(1, abase, 3);
        mma_block(0);                    // ks=2

        if (kt + 1 < KT) {
            CP_WAIT(0);                  // drains stage kt+1 only (kt+2 uncommitted)
            load_frag(0, sb + ((kt + 1) % S) * STAGE, 0);   // prefetch next ks=0
        }
        mma_block(1);                    // ks=3
        CP_COMMIT();                     // name stage kt+2's group
    }

    // Epilogue: direct float2 stores
#pragma unroll
    for (int t = 0; t < 4; t++) {
        const int r0 = m0 + wm * 64 + t * 16 + gid;
        float* y0 = Y + (size_t)r0 * D_OUT + n0 + wn * 64 + tig * 2;
        float* y1 = y0 + (size_t)8 * D_OUT;
#pragma unroll
        for (int n = 0; n < 8; n++) {
            *(float2*)(y0 + n * 8) = make_float2(acc[t][n][0], acc[t][n][1]);
            *(float2*)(y1 + n * 8) = make_float2(acc[t][n][2], acc[t][n][3]);
        }
    }
}

// ------------------------------- launcher ----------------------------------
extern "C" void kernel_launch(void* const* d_in, const int* in_sizes, int n_in,
                              void* d_out, int out_size) {
    const float* X  = (const float*)d_in[0];
    const float* Wq = (const float*)d_in[1];
    const float* c1 = (const float*)d_in[2];
    const float* ck = (const float*)d_in[3];
    const float* L1 = (const float*)d_in[4];
    const float* L2 = (const float*)d_in[5];
    float* Y = (float*)d_out;

    cudaFuncSetAttribute(gemm_kernel, cudaFuncAttributeMaxDynamicSharedMemorySize, SMEM_SZ);

    pack_x_kernel<<<NROWS, 256>>>(X);
    pack_w_kernel<<<dim3(D_OUT / 64, D_IN / 64), 256>>>(Wq, c1, ck, L1, L2);
    gemm_kernel<<<dim3(D_OUT / BN, NROWS / BM), 128, SMEM_SZ>>>(Y);
}

// round 17
// speedup vs baseline: 1.0212x; 1.0033x over previous
#include <cuda_runtime.h>
#include <cuda_fp16.h>
#include <cstdint>

// Y = X @ (W_nf4 * c1 * c_kbit_2) + (X@L1)@L2  ==  X @ W'  with
//   W' = W_nf4*c1*c_kbit_2 + L1@L2   (rank-16 update folded into the weight)
// R16->R17: run pack_x and pack_w CONCURRENTLY via graph-capturable stream
// fork/join (events), instead of serially. Both are DRAM-bound; overlapped
// they approach the joint 44us memory floor vs 57us serial. All three
// kernels byte-identical to R16 (KPAD=4160, R6/R8 GEMM pipeline, KT=64).
//   Xe fp16 [8192,4160] (cols 0..4095 = fp16(X))
//   We fp16 [4096,4160] (cols 0..4095 = fp16(W^T + (L1@L2)^T))

static constexpr int D_IN  = 4096;
static constexpr int D_OUT = 4096;
static constexpr int NROWS = 8192;
static constexpr int KPAD  = 4160;    // 8320B stride = 65 x 128B (proven)

static constexpr int BM = 128, BN = 128, BK = 64, S = 3;
static constexpr int KT = D_IN / BK;              // 64
static constexpr int ABYTES = BM * BK * 2;        // 16384
static constexpr int BBYTES = BN * BK * 2;        // 16384
static constexpr int STAGE  = ABYTES + BBYTES;    // 32768
static constexpr int SMEM_SZ = S * STAGE;         // 98304 (2 CTAs/SM)

__device__ __align__(16) __half g_Xe[(size_t)NROWS * KPAD];   // 68 MB
__device__ __align__(16) __half g_We[(size_t)D_OUT * KPAD];   // 34 MB

// ------------------------------ PTX helpers -------------------------------
__device__ __forceinline__ void cp16(uint32_t dst, const void* src) {
    asm volatile("cp.async.cg.shared.global [%0], [%1], 16;"
                 :: "r"(dst), "l"(__cvta_generic_to_global(src)) : "memory");
}
#define CP_COMMIT() asm volatile("cp.async.commit_group;" ::: "memory")
#define CP_WAIT(n)  asm volatile("cp.async.wait_group %0;" :: "n"(n) : "memory")

#define LDSM4(r, a) \
    asm volatile("ldmatrix.sync.aligned.m8n8.x4.shared.b16 {%0,%1,%2,%3}, [%4];" \
        : "=r"((r)[0]), "=r"((r)[1]), "=r"((r)[2]), "=r"((r)[3]) : "r"(a))

#define MMA16816(d, a, b) \
    asm volatile("mma.sync.aligned.m16n8k16.row.col.f32.f16.f16.f32 " \
        "{%0,%1,%2,%3}, {%4,%5,%6,%7}, {%8,%9}, {%0,%1,%2,%3};" \
        : "+f"((d)[0]), "+f"((d)[1]), "+f"((d)[2]), "+f"((d)[3]) \
        : "r"((a)[0]), "r"((a)[1]), "r"((a)[2]), "r"((a)[3]), \
          "r"((b)[0]), "r"((b)[1]))

__device__ __forceinline__ uint32_t swz(uint32_t o) { return o ^ ((o >> 3) & 0x70); }

// ------------------- pack_X: fp32 -> fp16 convert (padded rows) ------------
__global__ void __launch_bounds__(256)
pack_x_kernel(const float* __restrict__ X) {
    const size_t row = blockIdx.x;
    const float* src = X + row * (size_t)D_IN;
    __half* dst = g_Xe + row * (size_t)KPAD;
#pragma unroll
    for (int i = 0; i < 2; i++) {
        const int c = threadIdx.x * 8 + i * 2048;
        float4 a = *(const float4*)(src + c);
        float4 b = *(const float4*)(src + c + 4);
        __half2 t0 = __floats2half2_rn(a.x, a.y);
        __half2 t1 = __floats2half2_rn(a.z, a.w);
        __half2 t2 = __floats2half2_rn(b.x, b.y);
        __half2 t3 = __floats2half2_rn(b.z, b.w);
        uint4 u;
        u.x = *(uint32_t*)&t0;
        u.y = *(uint32_t*)&t1;
        u.z = *(uint32_t*)&t2;
        u.w = *(uint32_t*)&t3;
        *(uint4*)(dst + c) = u;
    }
}

// -------- pack_W: dequant + rank-16 LoRA add + transpose to We -------------
__global__ void __launch_bounds__(256)
pack_w_kernel(const float* __restrict__ Wq, const float* __restrict__ c1p,
              const float* __restrict__ ck, const float* __restrict__ L1,
              const float* __restrict__ L2) {
    __shared__ float tile[64 * 65];      // dequantized W tile, tile[k*65+n]
    __shared__ float sL1[64 * 17];       // L1[k0+k][j]  at sL1[k*17+j]
    __shared__ float sL2[16 * 68];       // L2[j][n0+n] at sL2[j*68+n]
    const float c1 = *c1p;
    const int tid = threadIdx.x;
    const int n0 = blockIdx.x * 64, k0 = blockIdx.y * 64;

    {
        const int tq = tid & 15, tr = tid >> 4;
#pragma unroll
        for (int i = 0; i < 4; i++) {
            int kk = tr + 16 * i;
            int nc = tq * 4;
            size_t g = (size_t)(k0 + kk) * D_OUT + n0 + nc;
            float4 w = *(const float4*)(Wq + g);
            float4 s = *(const float4*)(ck + g);
            float* tp = tile + kk * 65 + nc;
            tp[0] = w.x * c1 * s.x;
            tp[1] = w.y * c1 * s.y;
            tp[2] = w.z * c1 * s.z;
            tp[3] = w.w * c1 * s.w;
        }
        int kr = tid >> 2, j4 = (tid & 3) * 4;
        float4 v1 = *(const float4*)(L1 + (size_t)(k0 + kr) * 16 + j4);
        float* lp = sL1 + kr * 17 + j4;
        lp[0] = v1.x; lp[1] = v1.y; lp[2] = v1.z; lp[3] = v1.w;
        int jj = tid >> 4, c = (tid & 15) * 4;
        float4 v2 = *(const float4*)(L2 + (size_t)jj * D_OUT + n0 + c);
        *(float4*)(sL2 + jj * 68 + c) = v2;
    }
    __syncthreads();

    const int k4 = (tid & 15) * 4;
    const int n4 = (tid >> 4) * 4;
    float acc[4][4];
#pragma unroll
    for (int i = 0; i < 4; i++)
#pragma unroll
        for (int q = 0; q < 4; q++)
            acc[i][q] = tile[(k4 + i) * 65 + n4 + q];

#pragma unroll
    for (int j = 0; j < 16; j++) {
        float l2q[4], l1i[4];
#pragma unroll
        for (int q = 0; q < 4; q++) l2q[q] = sL2[j * 68 + n4 + q];
#pragma unroll
        for (int i = 0; i < 4; i++) l1i[i] = sL1[(k4 + i) * 17 + j];
#pragma unroll
        for (int i = 0; i < 4; i++)
#pragma unroll
            for (int q = 0; q < 4; q++)
                acc[i][q] += l1i[i] * l2q[q];
    }

#pragma unroll
    for (int q = 0; q < 4; q++) {
        __half2 h0 = __floats2half2_rn(acc[0][q], acc[1][q]);
        __half2 h1 = __floats2half2_rn(acc[2][q], acc[3][q]);
        uint2 u;
        u.x = *(uint32_t*)&h0;
        u.y = *(uint32_t*)&h1;
        *(uint2*)(g_We + (size_t)(n0 + n4 + q) * KPAD + k0 + k4) = u;
    }
}

// ------------------------------ GEMM kernel --------------------------------
// Exact R6/R8 loop: 4 warps (2x2), warp tile 64x64, cross-iteration frag
// prefetch with deferred commit_group; sync -> load_frag(1) -> mma(0).
__global__ void __launch_bounds__(128, 2)
gemm_kernel(float* __restrict__ Y) {
    extern __shared__ char smem[];
    const uint32_t sb = (uint32_t)__cvta_generic_to_shared(smem);
    const int tid = threadIdx.x, wid = tid >> 5, lane = tid & 31;
    const int m0 = blockIdx.y * BM, n0 = blockIdx.x * BN;
    const int wm = wid & 1, wn = wid >> 1;
    const int gid = lane >> 2, tig = lane & 3;

    auto loadA = [&](int kt, int slot) {
        const __half* src = g_Xe + (size_t)m0 * KPAD + (size_t)kt * BK;
        uint32_t base = sb + slot * STAGE;
#pragma unroll
        for (int i = 0; i < 8; i++) {
            int idx = tid + i * 128;
            int r = idx >> 3, c = idx & 7;
            cp16(base + swz((uint32_t)(r * 128 + c * 16)),
                 src + (size_t)r * KPAD + c * 8);
        }
    };
    auto loadB = [&](int kt, int slot) {
        const __half* src = g_We + (size_t)n0 * KPAD + (size_t)kt * BK;
        uint32_t base = sb + slot * STAGE + ABYTES;
#pragma unroll
        for (int i = 0; i < 8; i++) {
            int idx = tid + i * 128;
            int r = idx >> 3, c = idx & 7;
            cp16(base + swz((uint32_t)(r * 128 + c * 16)),
                 src + (size_t)r * KPAD + c * 8);
        }
    };

    float acc[4][8][4];
#pragma unroll
    for (int t = 0; t < 4; t++)
#pragma unroll
        for (int n = 0; n < 8; n++)
#pragma unroll
            for (int j = 0; j < 4; j++) acc[t][n][j] = 0.f;

#pragma unroll
    for (int s = 0; s < S - 1; s++) { loadA(s, s); loadB(s, s); CP_COMMIT(); }

    const uint32_t a_row = (uint32_t)(wm * 64 + (lane & 15));
    const uint32_t a_chk = (uint32_t)(lane >> 4);
    const uint32_t b_row = (uint32_t)(wn * 64 + ((lane >> 4) & 1) * 8 + (lane & 7));
    const uint32_t b_chk = (uint32_t)((lane >> 3) & 1);

    uint32_t af[2][4][4];
    uint32_t bf[2][8][2];

    auto load_frag = [&](int buf, uint32_t abase, int ks) {
        const uint32_t bbase = abase + ABYTES;
#pragma unroll
        for (int t = 0; t < 4; t++) {
            uint32_t off = (a_row + t * 16) * 128 + (a_chk + ks * 2) * 16;
            LDSM4(af[buf][t], abase + swz(off));
        }
#pragma unroll
        for (int g = 0; g < 4; g++) {
            uint32_t off = (b_row + g * 16) * 128 + (b_chk + ks * 2) * 16;
            uint32_t r[4];
            LDSM4(r, bbase + swz(off));
            bf[buf][2 * g][0] = r[0];     bf[buf][2 * g][1] = r[1];
            bf[buf][2 * g + 1][0] = r[2]; bf[buf][2 * g + 1][1] = r[3];
        }
    };
    auto mma_block = [&](int buf) {
#pragma unroll
        for (int t = 0; t < 4; t++)
#pragma unroll
            for (int n = 0; n < 8; n++)
                MMA16816(acc[t][n], af[buf][t], bf[buf][n]);
    };

    // Wait stage 0 (leave stage 1 in flight), prefetch its ks=0 fragments.
    CP_WAIT(1);
    __syncthreads();
    load_frag(0, sb + 0 * STAGE, 0);

    for (int kt = 0; kt < KT; kt++) {
        const uint32_t abase = sb + (kt % S) * STAGE;
        // Barrier: about to overwrite slot (kt+2)%S == (kt-1)%S. All reads of
        // stage kt-1 (and the prefetch read of stage kt) happened before here.
        __syncthreads();

        load_frag(1, abase, 1);          // ks=1 frags first (critical path)
        mma_block(0);                    // ks=0 (prefetched)

        if (kt + 2 < KT) {               // issue next stage UNCOMMITTED
            loadA(kt + 2, (kt + 2) % S);
            loadB(kt + 2, (kt + 2) % S);
        }

        load_frag(0, abase, 2);
        mma_block(1);                    // ks=1

        load_frag(1, abase, 3);
        mma_block(0);                    // ks=2

        if (kt + 1 < KT) {
            CP_WAIT(0);                  // drains stage kt+1 only (kt+2 uncommitted)
            load_frag(0, sb + ((kt + 1) % S) * STAGE, 0);   // prefetch next ks=0
        }
        mma_block(1);                    // ks=3
        CP_COMMIT();                     // name stage kt+2's group
    }

    // Epilogue: direct float2 stores
#pragma unroll
    for (int t = 0; t < 4; t++) {
        const int r0 = m0 + wm * 64 + t * 16 + gid;
        float* y0 = Y + (size_t)r0 * D_OUT + n0 + wn * 64 + tig * 2;
        float* y1 = y0 + (size_t)8 * D_OUT;
#pragma unroll
        for (int n = 0; n < 8; n++) {
            *(float2*)(y0 + n * 8) = make_float2(acc[t][n][0], acc[t][n][1]);
            *(float2*)(y1 + n * 8) = make_float2(acc[t][n][2], acc[t][n][3]);
        }
    }
}

// ------------------------------- launcher ----------------------------------
// pack_x runs on a forked side stream, pack_w on the main (capture) stream;
// event fork/join keeps the graph well-formed and lets the two DRAM-bound
// packs overlap. Streams/events are host-side objects created once (no device
// memory); identical work is recorded on every call.
extern "C" void kernel_launch(void* const* d_in, const int* in_sizes, int n_in,
                              void* d_out, int out_size) {
    const float* X  = (const float*)d_in[0];
    const float* Wq = (const float*)d_in[1];
    const float* c1 = (const float*)d_in[2];
    const float* ck = (const float*)d_in[3];
    const float* L1 = (const float*)d_in[4];
    const float* L2 = (const float*)d_in[5];
    float* Y = (float*)d_out;

    static cudaStream_t s_side = nullptr;
    static cudaEvent_t  e_fork = nullptr, e_join = nullptr;
    if (s_side == nullptr) {
        cudaStreamCreateWithFlags(&s_side, cudaStreamNonBlocking);
        cudaEventCreateWithFlags(&e_fork, cudaEventDisableTiming);
        cudaEventCreateWithFlags(&e_join, cudaEventDisableTiming);
        cudaFuncSetAttribute(gemm_kernel,
                             cudaFuncAttributeMaxDynamicSharedMemorySize, SMEM_SZ);
    }

    // Fork: side stream joins the (possibly capturing) legacy stream.
    cudaEventRecord(e_fork, 0);
    cudaStreamWaitEvent(s_side, e_fork, 0);

    pack_x_kernel<<<NROWS, 256, 0, s_side>>>(X);
    pack_w_kernel<<<dim3(D_OUT / 64, D_IN / 64), 256>>>(Wq, c1, ck, L1, L2);

    // Join: main stream waits for pack_x before the GEMM.
    cudaEventRecord(e_join, s_side);
    cudaStreamWaitEvent(0, e_join, 0);

    gemm_kernel<<<dim3(D_OUT / BN, NROWS / BM), 128, SMEM_SZ>>>(Y);
}